// round 1
// baseline (speedup 1.0000x reference)
#include <cuda_runtime.h>
#include <cstdint>

// Problem shape (fixed by the reference)
#define Bn 4
#define Ln 2048
#define Dn 1024
#define Hn 16
// dk = 64, 3*Dn = 3072

// Scratch (allocation-free rule: __device__ globals)
__device__ float g_qkv[(size_t)Bn * Ln * 3 * Dn];  // 100.7 MB: x@W1+b1, layout (B*L, 3D)
__device__ float g_ctx[(size_t)Bn * Ln * Dn];      // 33.6 MB: attention output (B, L, D)

// ---------------------------------------------------------------------------
// SGEMM: C[M,N] = A[M,K] @ W[K,N] + bias[N]
// Classic 128x128x8 tiling, 8x8 per thread, 256 threads, As stored transposed.
// ---------------------------------------------------------------------------
__global__ __launch_bounds__(256) void sgemm_bias(
    int M, int N, int K,
    const float* __restrict__ A, const float* __restrict__ W,
    const float* __restrict__ bias, float* __restrict__ C)
{
    __shared__ float As[8][128];   // [k][m] (transposed)
    __shared__ float Bs[8][128];   // [k][n]

    const int tid  = threadIdx.x;
    const int tcol = tid & 15;     // 0..15  -> n block of 8
    const int trow = tid >> 4;     // 0..15  -> m block of 8
    const int bx = blockIdx.x, by = blockIdx.y;

    A += (size_t)by * 128 * K;
    W += bx * 128;
    C += (size_t)by * 128 * N + bx * 128;

    const int aRow = tid >> 1;         // 0..127
    const int aCol = (tid & 1) * 4;    // 0 or 4
    const int bRow = tid >> 5;         // 0..7
    const int bCol = (tid & 31) * 4;   // 0..124

    float acc[8][8];
#pragma unroll
    for (int i = 0; i < 8; i++)
#pragma unroll
        for (int j = 0; j < 8; j++) acc[i][j] = 0.f;

    for (int k0 = 0; k0 < K; k0 += 8) {
        float4 a4 = *(const float4*)(A + (size_t)aRow * K + k0 + aCol);
        As[aCol + 0][aRow] = a4.x;
        As[aCol + 1][aRow] = a4.y;
        As[aCol + 2][aRow] = a4.z;
        As[aCol + 3][aRow] = a4.w;
        *(float4*)(&Bs[bRow][bCol]) =
            *(const float4*)(W + (size_t)(k0 + bRow) * N + bCol);
        __syncthreads();

#pragma unroll
        for (int k = 0; k < 8; k++) {
            float rm[8], rn[8];
            *(float4*)(rm)     = *(const float4*)(&As[k][trow * 8]);
            *(float4*)(rm + 4) = *(const float4*)(&As[k][trow * 8 + 4]);
            *(float4*)(rn)     = *(const float4*)(&Bs[k][tcol * 8]);
            *(float4*)(rn + 4) = *(const float4*)(&Bs[k][tcol * 8 + 4]);
#pragma unroll
            for (int i = 0; i < 8; i++)
#pragma unroll
                for (int j = 0; j < 8; j++) acc[i][j] += rm[i] * rn[j];
        }
        __syncthreads();
    }

#pragma unroll
    for (int i = 0; i < 8; i++) {
#pragma unroll
        for (int j = 0; j < 8; j += 4) {
            const int n = tcol * 8 + j;
            float4 o;
            o.x = acc[i][j + 0] + bias[bx * 128 + n + 0];
            o.y = acc[i][j + 1] + bias[bx * 128 + n + 1];
            o.z = acc[i][j + 2] + bias[bx * 128 + n + 2];
            o.w = acc[i][j + 3] + bias[bx * 128 + n + 3];
            *(float4*)(&C[(size_t)(trow * 8 + i) * N + n]) = o;
        }
    }
}

// ---------------------------------------------------------------------------
// Flash-style attention with the reference's exact masked-softmax semantics:
//   masked score := 0.0f (the 2.2e-308 fill underflows to 0 in fp32)
//   softmax denominator INCLUDES exp(0 - m) for masked columns
//   masked attention weights are zeroed before attn @ V
//
// Block: 64 q-rows for one (b,h). Loop over K/V in tiles of 32 rows.
// 256 threads = 16x16; thread owns 4 q-rows x {2 k-cols | 4 d-cols}.
// Q and K staged TRANSPOSED ([d][q] / [d][k]) for vectorized smem loads.
// P staged transposed ([k][q]) so the PV GEMM also vector-loads.
// ---------------------------------------------------------------------------
__global__ __launch_bounds__(256) void attn_kernel(
    const float* __restrict__ qkv, const int* __restrict__ mask,
    float* __restrict__ ctx)
{
    __shared__ float Qs[64][68];   // [d][q], pad 68 -> 16B-aligned rows
    __shared__ float Ks[64][34];   // [d][k], pad 34 -> 8B-aligned rows
    __shared__ float Vs[32][64];   // [k][d], natural
    __shared__ float Ps[32][68];   // [k][q], pad 68

    const int tid = threadIdx.x;
    const int tx = tid & 15;       // k-cols (S) / d-cols (PV)
    const int ty = tid >> 4;       // q-rows (x4)
    const int bh = blockIdx.y;
    const int b = bh >> 4, h = bh & 15;
    const int q0 = blockIdx.x * 64;

    const float* Qg = qkv + (size_t)b * Ln * 3 * Dn + h * 64;
    const float* Kg = Qg + Dn;
    const float* Vg = Qg + 2 * Dn;
    const int*   Mg = mask + (size_t)b * Ln * Ln;

    // Stage Q tile (64 q x 64 d), transposed into Qs[d][q]
#pragma unroll
    for (int it = 0; it < 4; it++) {
        const int idx = tid + it * 256;          // 1024 float4s
        const int q = idx >> 4, d4 = (idx & 15) * 4;
        float4 v = *(const float4*)(Qg + (size_t)(q0 + q) * 3072 + d4);
        Qs[d4 + 0][q] = v.x; Qs[d4 + 1][q] = v.y;
        Qs[d4 + 2][q] = v.z; Qs[d4 + 3][q] = v.w;
    }

    float o[4][4];
    float m_i[4], l_i[4];
#pragma unroll
    for (int i = 0; i < 4; i++) {
        m_i[i] = -1e30f; l_i[i] = 0.f;
#pragma unroll
        for (int j = 0; j < 4; j++) o[i][j] = 0.f;
    }
    __syncthreads();

    for (int kt = 0; kt < Ln / 32; kt++) {
        const int kb = kt * 32;
        // Stage K (transposed) and V (natural): 32 rows x 64 d each
#pragma unroll
        for (int it = 0; it < 2; it++) {
            const int idx = tid + it * 256;      // 512 float4s
            const int kk = idx >> 4, d4 = (idx & 15) * 4;
            float4 kv = *(const float4*)(Kg + (size_t)(kb + kk) * 3072 + d4);
            Ks[d4 + 0][kk] = kv.x; Ks[d4 + 1][kk] = kv.y;
            Ks[d4 + 2][kk] = kv.z; Ks[d4 + 3][kk] = kv.w;
            *(float4*)(&Vs[kk][d4]) =
                *(const float4*)(Vg + (size_t)(kb + kk) * 3072 + d4);
        }
        __syncthreads();

        // S = Q @ K^T over d=64; thread fragment 4q x 2k
        float s[4][2] = {{0.f, 0.f}, {0.f, 0.f}, {0.f, 0.f}, {0.f, 0.f}};
#pragma unroll 16
        for (int d = 0; d < 64; d++) {
            float4 q4 = *(const float4*)(&Qs[d][ty * 4]);
            float2 k2 = *(const float2*)(&Ks[d][tx * 2]);
            s[0][0] += q4.x * k2.x; s[0][1] += q4.x * k2.y;
            s[1][0] += q4.y * k2.x; s[1][1] += q4.y * k2.y;
            s[2][0] += q4.z * k2.x; s[2][1] += q4.z * k2.y;
            s[3][0] += q4.w * k2.x; s[3][1] += q4.w * k2.y;
        }

        // Mask + online softmax (per q-row, reduce over 16 tx lanes)
        float p[4][2];
#pragma unroll
        for (int i = 0; i < 4; i++) {
            int2 mv = *(const int2*)(Mg + (size_t)(q0 + ty * 4 + i) * Ln + kb + tx * 2);
            const float s0 = (mv.x != 0) ? s[i][0] * 0.125f : 0.0f;
            const float s1 = (mv.y != 0) ? s[i][1] * 0.125f : 0.0f;
            float mx = fmaxf(s0, s1);
#pragma unroll
            for (int off = 8; off; off >>= 1)
                mx = fmaxf(mx, __shfl_xor_sync(0xffffffffu, mx, off));
            const float mnew = fmaxf(m_i[i], mx);
            const float e0 = __expf(s0 - mnew);
            const float e1 = __expf(s1 - mnew);
            float rs = e0 + e1;                 // masked cols DO count in the sum
#pragma unroll
            for (int off = 8; off; off >>= 1)
                rs += __shfl_xor_sync(0xffffffffu, rs, off);
            const float alpha = __expf(m_i[i] - mnew);
            l_i[i] = l_i[i] * alpha + rs;
            m_i[i] = mnew;
            p[i][0] = (mv.x != 0) ? e0 : 0.0f;  // masked cols excluded from PV
            p[i][1] = (mv.y != 0) ? e1 : 0.0f;
#pragma unroll
            for (int j = 0; j < 4; j++) o[i][j] *= alpha;
        }

        // Store P transposed: Ps[k][q] (float4 over the 4 q-rows)
#pragma unroll
        for (int j = 0; j < 2; j++) {
            float4 pv = make_float4(p[0][j], p[1][j], p[2][j], p[3][j]);
            *(float4*)(&Ps[tx * 2 + j][ty * 4]) = pv;
        }
        __syncthreads();

        // O[q][d] += sum_k Ps[k][q] * Vs[k][d]; thread fragment 4q x 4d
#pragma unroll 8
        for (int k = 0; k < 32; k++) {
            float4 pq = *(const float4*)(&Ps[k][ty * 4]);
            float4 vv = *(const float4*)(&Vs[k][tx * 4]);
            o[0][0] += pq.x * vv.x; o[0][1] += pq.x * vv.y;
            o[0][2] += pq.x * vv.z; o[0][3] += pq.x * vv.w;
            o[1][0] += pq.y * vv.x; o[1][1] += pq.y * vv.y;
            o[1][2] += pq.y * vv.z; o[1][3] += pq.y * vv.w;
            o[2][0] += pq.z * vv.x; o[2][1] += pq.z * vv.y;
            o[2][2] += pq.z * vv.z; o[2][3] += pq.z * vv.w;
            o[3][0] += pq.w * vv.x; o[3][1] += pq.w * vv.y;
            o[3][2] += pq.w * vv.z; o[3][3] += pq.w * vv.w;
        }
        __syncthreads();
    }

    // Normalize and write ctx as (B, L, D) with head h at columns h*64..h*64+63
#pragma unroll
    for (int i = 0; i < 4; i++) {
        const float inv = 1.0f / l_i[i];
        float4 ov = make_float4(o[i][0] * inv, o[i][1] * inv,
                                o[i][2] * inv, o[i][3] * inv);
        *(float4*)(ctx + (size_t)(b * Ln + q0 + ty * 4 + i) * Dn + h * 64 + tx * 4) = ov;
    }
}

// ---------------------------------------------------------------------------
extern "C" void kernel_launch(void* const* d_in, const int* in_sizes, int n_in,
                              void* d_out, int out_size)
{
    const float* x   = (const float*)d_in[0];  // (B, L, D) fp32
    const int*   msk = (const int*)d_in[1];    // (B, L, L) int32
    const float* W1  = (const float*)d_in[2];  // (D, 3D)
    const float* b1  = (const float*)d_in[3];  // (3D,)
    const float* W2  = (const float*)d_in[4];  // (D, D)
    const float* b2  = (const float*)d_in[5];  // (D,)
    float* out = (float*)d_out;                // (B, L, D)

    float *qkv = nullptr, *ctx = nullptr;
    cudaGetSymbolAddress((void**)&qkv, g_qkv);
    cudaGetSymbolAddress((void**)&ctx, g_ctx);

    const int M = Bn * Ln;  // 8192

    // 1) QKV projection: (8192,1024) @ (1024,3072) + b1
    sgemm_bias<<<dim3(3 * Dn / 128, M / 128), 256>>>(M, 3 * Dn, Dn, x, W1, b1, qkv);

    // 2) Masked attention per (b,h), 64 q-rows per block
    attn_kernel<<<dim3(Ln / 64, Bn * Hn), 256>>>(qkv, msk, ctx);

    // 3) Output projection: (8192,1024) @ (1024,1024) + b2
    sgemm_bias<<<dim3(Dn / 128, M / 128), 256>>>(M, Dn, Dn, ctx, W2, b2, out);
}

// round 2
// speedup vs baseline: 1.9941x; 1.9941x over previous
#include <cuda_runtime.h>
#include <cstdint>

// Problem shape (fixed by the reference)
#define Bn 4
#define Ln 2048
#define Dn 1024
#define Hn 16
// dk = 64, 3*Dn = 3072

// Scratch (allocation-free rule: __device__ globals)
__device__ float g_qkv[(size_t)Bn * Ln * 3 * Dn];  // 100.7 MB
__device__ float g_ctx[(size_t)Bn * Ln * Dn];      // 33.6 MB

// ---------------------------------------------------------------------------
// TF32 helpers
// ---------------------------------------------------------------------------
__device__ __forceinline__ uint32_t f2tf(float x) {
    uint32_t r;
    asm("cvt.rna.tf32.f32 %0, %1;" : "=r"(r) : "f"(x));
    return r;
}

__device__ __forceinline__ void mma_tf32(float c[4], const uint32_t a[4],
                                         const uint32_t b[2]) {
    asm volatile(
        "mma.sync.aligned.m16n8k8.row.col.f32.tf32.tf32.f32 "
        "{%0,%1,%2,%3}, {%4,%5,%6,%7}, {%8,%9}, {%0,%1,%2,%3};"
        : "+f"(c[0]), "+f"(c[1]), "+f"(c[2]), "+f"(c[3])
        : "r"(a[0]), "r"(a[1]), "r"(a[2]), "r"(a[3]), "r"(b[0]), "r"(b[1]));
}

// ---------------------------------------------------------------------------
// TF32 GEMM: C[M,N] = A[M,K] @ W[K,N] + bias[N]
// 128x128 block, BK=16 double-buffered, 8 warps (2x4), warp tile 64x32.
// mma.m16n8k8: A frag from As[k][m] (transposed), B frag from Bs[k][n].
// ---------------------------------------------------------------------------
#define GBK 16
__global__ __launch_bounds__(256) void tf32_gemm_bias(
    int M, int N, int K,
    const float* __restrict__ A, const float* __restrict__ W,
    const float* __restrict__ bias, float* __restrict__ C)
{
    __shared__ uint32_t As[2][GBK][132];   // [k][m], pad 132
    __shared__ uint32_t Bs[2][GBK][132];   // [k][n], pad 132

    const int tid  = threadIdx.x;
    const int lane = tid & 31;
    const int warp = tid >> 5;
    const int wm = warp >> 2;      // 0..1 -> m base wm*64
    const int wn = warp & 3;       // 0..3 -> n base wn*32
    const int g  = lane >> 2;      // groupID 0..7
    const int tig = lane & 3;      // thread-in-group 0..3

    const int bx = blockIdx.x, by = blockIdx.y;
    A += (size_t)by * 128 * K;
    W += bx * 128;
    C += (size_t)by * 128 * N + bx * 128;

    // Staging assignments
    const int ar = tid >> 1;           // A row 0..127
    const int ac = (tid & 1) * 8;      // A col base (two float4)
    const int br = tid >> 4;           // B k-row 0..15
    const int bc = (tid & 15) * 8;     // B n base (two float4)

    float acc[4][4][4];
#pragma unroll
    for (int mi = 0; mi < 4; mi++)
#pragma unroll
        for (int ni = 0; ni < 4; ni++)
#pragma unroll
            for (int j = 0; j < 4; j++) acc[mi][ni][j] = 0.f;

    float4 pa0, pa1, pb0, pb1;

    // Fetch tile k0 into registers
    auto fetch = [&](int k0) {
        pa0 = *(const float4*)(A + (size_t)ar * K + k0 + ac);
        pa1 = *(const float4*)(A + (size_t)ar * K + k0 + ac + 4);
        pb0 = *(const float4*)(W + (size_t)(k0 + br) * N + bc);
        pb1 = *(const float4*)(W + (size_t)(k0 + br) * N + bc + 4);
    };
    // Stage registers into smem buffer (with tf32 conversion)
    auto stage = [&](int buf) {
        As[buf][ac + 0][ar] = f2tf(pa0.x);
        As[buf][ac + 1][ar] = f2tf(pa0.y);
        As[buf][ac + 2][ar] = f2tf(pa0.z);
        As[buf][ac + 3][ar] = f2tf(pa0.w);
        As[buf][ac + 4][ar] = f2tf(pa1.x);
        As[buf][ac + 5][ar] = f2tf(pa1.y);
        As[buf][ac + 6][ar] = f2tf(pa1.z);
        As[buf][ac + 7][ar] = f2tf(pa1.w);
        Bs[buf][br][bc + 0] = f2tf(pb0.x);
        Bs[buf][br][bc + 1] = f2tf(pb0.y);
        Bs[buf][br][bc + 2] = f2tf(pb0.z);
        Bs[buf][br][bc + 3] = f2tf(pb0.w);
        Bs[buf][br][bc + 4] = f2tf(pb1.x);
        Bs[buf][br][bc + 5] = f2tf(pb1.y);
        Bs[buf][br][bc + 6] = f2tf(pb1.z);
        Bs[buf][br][bc + 7] = f2tf(pb1.w);
    };

    fetch(0);
    stage(0);
    __syncthreads();

    int buf = 0;
    const int nTiles = K / GBK;
    for (int kt = 0; kt < nTiles; kt++) {
        const int kn = (kt + 1) * GBK;
        if (kn < K) fetch(kn);

        // Compute on buffer `buf`
#pragma unroll
        for (int ks = 0; ks < 2; ks++) {
            uint32_t a[4][4], b[4][2];
#pragma unroll
            for (int mi = 0; mi < 4; mi++) {
                const int m = wm * 64 + mi * 16 + g;
                a[mi][0] = As[buf][ks * 8 + tig][m];
                a[mi][1] = As[buf][ks * 8 + tig][m + 8];
                a[mi][2] = As[buf][ks * 8 + tig + 4][m];
                a[mi][3] = As[buf][ks * 8 + tig + 4][m + 8];
            }
#pragma unroll
            for (int ni = 0; ni < 4; ni++) {
                const int n = wn * 32 + ni * 8 + g;
                b[ni][0] = Bs[buf][ks * 8 + tig][n];
                b[ni][1] = Bs[buf][ks * 8 + tig + 4][n];
            }
#pragma unroll
            for (int mi = 0; mi < 4; mi++)
#pragma unroll
                for (int ni = 0; ni < 4; ni++)
                    mma_tf32(acc[mi][ni], a[mi], b[ni]);
        }

        if (kn < K) {
            stage(buf ^ 1);
            buf ^= 1;
            __syncthreads();
        }
    }

    // Epilogue: c0 (g, 2t), c1 (g, 2t+1), c2 (g+8, 2t), c3 (g+8, 2t+1)
#pragma unroll
    for (int mi = 0; mi < 4; mi++) {
#pragma unroll
        for (int ni = 0; ni < 4; ni++) {
            const int row = wm * 64 + mi * 16 + g;
            const int col = wn * 32 + ni * 8 + 2 * tig;
            const float bz0 = bias[bx * 128 + col];
            const float bz1 = bias[bx * 128 + col + 1];
            float2 o0 = make_float2(acc[mi][ni][0] + bz0, acc[mi][ni][1] + bz1);
            float2 o1 = make_float2(acc[mi][ni][2] + bz0, acc[mi][ni][3] + bz1);
            *(float2*)(&C[(size_t)row * N + col]) = o0;
            *(float2*)(&C[(size_t)(row + 8) * N + col]) = o1;
        }
    }
}

// ---------------------------------------------------------------------------
// Flash attention with TF32 tensor-core GEMMs.
// Reference semantics: masked score := 0.0f, INCLUDED in softmax max and
// denominator, but masked attention weight := 0 before attn @ V.
//
// Block: 128 q-rows for one (b,h); 8 warps, each owns 16 q-rows.
// K-tile: 64 keys. S = Q@K^T and O += P@V both via mma.m16n8k8 tf32.
// P round-trips through per-warp smem region (no cross-warp exchange).
// ---------------------------------------------------------------------------
#define QP 132   // Qs row pad (q dim)
#define KP 68    // Ks/Vs row pad
#define PP 132   // Ps row pad (q dim)
#define ATTN_SMEM_WORDS (64*QP + 64*KP + 64*KP + 64*PP)

__global__ __launch_bounds__(256) void attn_mma(
    const float* __restrict__ qkv, const int* __restrict__ mask,
    float* __restrict__ ctx)
{
    extern __shared__ uint32_t dsm[];
    uint32_t* Qs = dsm;                       // [64 d][QP]  (A layout [k][m])
    uint32_t* Ks = Qs + 64 * QP;              // [64 d][KP]  (B layout [k][n])
    uint32_t* Vs = Ks + 64 * KP;              // [64 kcol][KP] (B layout [k][n])
    uint32_t* Ps = Vs + 64 * KP;              // [64 kcol][PP] (A layout [k][m])

    const int tid  = threadIdx.x;
    const int lane = tid & 31;
    const int warp = tid >> 5;
    const int g  = lane >> 2;
    const int tig = lane & 3;
    const int qw = warp * 16;                 // warp's q base within block

    const int bh = blockIdx.y;
    const int b = bh >> 4, h = bh & 15;
    const int q0 = blockIdx.x * 128;

    const float* Qg = qkv + (size_t)b * Ln * 3 * Dn + h * 64;
    const float* Kg = Qg + Dn;
    const float* Vg = Qg + 2 * Dn;
    const int*   Mg = mask + (size_t)b * Ln * Ln;

    // Stage Q tile (128 q x 64 d) transposed -> Qs[d][q], tf32
#pragma unroll
    for (int it = 0; it < 8; it++) {
        const int idx = tid + it * 256;       // 2048 float4
        const int q = idx >> 4, d4 = (idx & 15) * 4;
        float4 v = *(const float4*)(Qg + (size_t)(q0 + q) * 3072 + d4);
        Qs[(d4 + 0) * QP + q] = f2tf(v.x);
        Qs[(d4 + 1) * QP + q] = f2tf(v.y);
        Qs[(d4 + 2) * QP + q] = f2tf(v.z);
        Qs[(d4 + 3) * QP + q] = f2tf(v.w);
    }

    float o[8][4];
    float m_i[2] = {-1e30f, -1e30f};
    float l_i[2] = {0.f, 0.f};
#pragma unroll
    for (int ni = 0; ni < 8; ni++)
#pragma unroll
        for (int j = 0; j < 4; j++) o[ni][j] = 0.f;

    for (int kt = 0; kt < Ln / 64; kt++) {
        const int kb = kt * 64;
        __syncthreads();   // previous iteration's PV reads done before overwrite

        // Stage K transposed -> Ks[d][kcol]; V natural -> Vs[kcol][d]
#pragma unroll
        for (int it = 0; it < 4; it++) {
            const int idx = tid + it * 256;   // 1024 float4
            const int kk = idx >> 4, d4 = (idx & 15) * 4;
            float4 kv = *(const float4*)(Kg + (size_t)(kb + kk) * 3072 + d4);
            Ks[(d4 + 0) * KP + kk] = f2tf(kv.x);
            Ks[(d4 + 1) * KP + kk] = f2tf(kv.y);
            Ks[(d4 + 2) * KP + kk] = f2tf(kv.z);
            Ks[(d4 + 3) * KP + kk] = f2tf(kv.w);
            float4 vv = *(const float4*)(Vg + (size_t)(kb + kk) * 3072 + d4);
            uint4 vt;
            vt.x = f2tf(vv.x); vt.y = f2tf(vv.y);
            vt.z = f2tf(vv.z); vt.w = f2tf(vv.w);
            *(uint4*)(&Vs[kk * KP + d4]) = vt;
        }
        __syncthreads();

        // S = Q @ K^T : warp computes 16q x 64k
        float s[8][4];
#pragma unroll
        for (int ni = 0; ni < 8; ni++)
#pragma unroll
            for (int j = 0; j < 4; j++) s[ni][j] = 0.f;

#pragma unroll
        for (int k8 = 0; k8 < 8; k8++) {
            uint32_t a[4], bfr[2];
            a[0] = Qs[(k8 * 8 + tig) * QP + qw + g];
            a[1] = Qs[(k8 * 8 + tig) * QP + qw + g + 8];
            a[2] = Qs[(k8 * 8 + tig + 4) * QP + qw + g];
            a[3] = Qs[(k8 * 8 + tig + 4) * QP + qw + g + 8];
#pragma unroll
            for (int ni = 0; ni < 8; ni++) {
                bfr[0] = Ks[(k8 * 8 + tig) * KP + ni * 8 + g];
                bfr[1] = Ks[(k8 * 8 + tig + 4) * KP + ni * 8 + g];
                mma_tf32(s[ni], a, bfr);
            }
        }

        // Mask + online softmax. Thread owns 2 q-rows: g and g+8.
#pragma unroll
        for (int ri = 0; ri < 2; ri++) {
            const int qrow = q0 + qw + g + ri * 8;
            unsigned mbits = 0;
            float mx = -1e30f;
#pragma unroll
            for (int ni = 0; ni < 8; ni++) {
                int2 mv = *(const int2*)(Mg + (size_t)qrow * Ln + kb + ni * 8 + 2 * tig);
                float s0 = (mv.x != 0) ? s[ni][ri * 2 + 0] * 0.125f : 0.0f;
                float s1 = (mv.y != 0) ? s[ni][ri * 2 + 1] * 0.125f : 0.0f;
                if (mv.x != 0) mbits |= 1u << (ni * 2);
                if (mv.y != 0) mbits |= 2u << (ni * 2);
                s[ni][ri * 2 + 0] = s0;
                s[ni][ri * 2 + 1] = s1;
                mx = fmaxf(mx, fmaxf(s0, s1));
            }
            mx = fmaxf(mx, __shfl_xor_sync(0xffffffffu, mx, 1));
            mx = fmaxf(mx, __shfl_xor_sync(0xffffffffu, mx, 2));
            const float mnew = fmaxf(m_i[ri], mx);
            const float alpha = __expf(m_i[ri] - mnew);
            m_i[ri] = mnew;
            float rs = 0.f;
#pragma unroll
            for (int ni = 0; ni < 8; ni++) {
                float e0 = __expf(s[ni][ri * 2 + 0] - mnew);
                float e1 = __expf(s[ni][ri * 2 + 1] - mnew);
                rs += e0 + e1;                       // masked cols count here
                s[ni][ri * 2 + 0] = (mbits & (1u << (ni * 2))) ? e0 : 0.f;
                s[ni][ri * 2 + 1] = (mbits & (2u << (ni * 2))) ? e1 : 0.f;
            }
            rs += __shfl_xor_sync(0xffffffffu, rs, 1);
            rs += __shfl_xor_sync(0xffffffffu, rs, 2);
            l_i[ri] = l_i[ri] * alpha + rs;
#pragma unroll
            for (int ni = 0; ni < 8; ni++) {
                o[ni][ri * 2 + 0] *= alpha;
                o[ni][ri * 2 + 1] *= alpha;
            }
        }

        // Store P transposed into this warp's own region: Ps[kcol][q]
#pragma unroll
        for (int ni = 0; ni < 8; ni++) {
            Ps[(ni * 8 + 2 * tig)     * PP + qw + g]     = f2tf(s[ni][0]);
            Ps[(ni * 8 + 2 * tig + 1) * PP + qw + g]     = f2tf(s[ni][1]);
            Ps[(ni * 8 + 2 * tig)     * PP + qw + g + 8] = f2tf(s[ni][2]);
            Ps[(ni * 8 + 2 * tig + 1) * PP + qw + g + 8] = f2tf(s[ni][3]);
        }
        __syncwarp();

        // O += P @ V : warp computes 16q x 64d over 64 kcols
#pragma unroll
        for (int k8 = 0; k8 < 8; k8++) {
            uint32_t a[4], bfr[2];
            a[0] = Ps[(k8 * 8 + tig) * PP + qw + g];
            a[1] = Ps[(k8 * 8 + tig) * PP + qw + g + 8];
            a[2] = Ps[(k8 * 8 + tig + 4) * PP + qw + g];
            a[3] = Ps[(k8 * 8 + tig + 4) * PP + qw + g + 8];
#pragma unroll
            for (int ni = 0; ni < 8; ni++) {
                bfr[0] = Vs[(k8 * 8 + tig) * KP + ni * 8 + g];
                bfr[1] = Vs[(k8 * 8 + tig + 4) * KP + ni * 8 + g];
                mma_tf32(o[ni], a, bfr);
            }
        }
    }

    // Normalize and write ctx (B, L, D), head h at cols h*64..h*64+63
    const float inv0 = 1.0f / l_i[0];
    const float inv1 = 1.0f / l_i[1];
    const int row0 = q0 + qw + g;
#pragma unroll
    for (int ni = 0; ni < 8; ni++) {
        const int col = h * 64 + ni * 8 + 2 * tig;
        float2 o0 = make_float2(o[ni][0] * inv0, o[ni][1] * inv0);
        float2 o1 = make_float2(o[ni][2] * inv1, o[ni][3] * inv1);
        *(float2*)(ctx + (size_t)(b * Ln + row0) * Dn + col) = o0;
        *(float2*)(ctx + (size_t)(b * Ln + row0 + 8) * Dn + col) = o1;
    }
}

// ---------------------------------------------------------------------------
extern "C" void kernel_launch(void* const* d_in, const int* in_sizes, int n_in,
                              void* d_out, int out_size)
{
    const float* x   = (const float*)d_in[0];  // (B, L, D) fp32
    const int*   msk = (const int*)d_in[1];    // (B, L, L) int32
    const float* W1  = (const float*)d_in[2];  // (D, 3D)
    const float* b1  = (const float*)d_in[3];  // (3D,)
    const float* W2  = (const float*)d_in[4];  // (D, D)
    const float* b2  = (const float*)d_in[5];  // (D,)
    float* out = (float*)d_out;                // (B, L, D)

    float *qkv = nullptr, *ctx = nullptr;
    cudaGetSymbolAddress((void**)&qkv, g_qkv);
    cudaGetSymbolAddress((void**)&ctx, g_ctx);

    const int M = Bn * Ln;  // 8192
    const int attnSmem = ATTN_SMEM_WORDS * 4;  // 102400 bytes
    cudaFuncSetAttribute(attn_mma, cudaFuncAttributeMaxDynamicSharedMemorySize,
                         attnSmem);

    // 1) QKV projection: (8192,1024) @ (1024,3072) + b1
    tf32_gemm_bias<<<dim3(3 * Dn / 128, M / 128), 256>>>(M, 3 * Dn, Dn, x, W1, b1, qkv);

    // 2) Masked attention per (b,h), 128 q-rows per block
    attn_mma<<<dim3(Ln / 128, Bn * Hn), 256, attnSmem>>>(qkv, msk, ctx);

    // 3) Output projection: (8192,1024) @ (1024,1024) + b2
    tf32_gemm_bias<<<dim3(Dn / 128, M / 128), 256>>>(M, Dn, Dn, ctx, W2, b2, out);
}

// round 5
// speedup vs baseline: 2.8838x; 1.4462x over previous
#include <cuda_runtime.h>
#include <cstdint>

// Problem shape (fixed by the reference)
#define Bn 4
#define Ln 2048
#define Dn 1024
#define Hn 16
// dk = 64, 3*Dn = 3072

// Scratch (allocation-free rule: __device__ globals)
__device__ float g_qkv[(size_t)Bn * Ln * 3 * Dn];          // 100.7 MB
__device__ float g_ctx[(size_t)Bn * Ln * Dn];              // 33.6 MB
__device__ uint32_t g_mpack[(size_t)Bn * Ln * Ln / 32];    // 2 MB packed mask

// ---------------------------------------------------------------------------
// TF32 helpers
// ---------------------------------------------------------------------------
__device__ __forceinline__ uint32_t f2tf(float x) {
    uint32_t r;
    asm("cvt.rna.tf32.f32 %0, %1;" : "=r"(r) : "f"(x));
    return r;
}
__device__ __forceinline__ float ex2(float x) {
    float r;
    asm("ex2.approx.ftz.f32 %0, %1;" : "=f"(r) : "f"(x));
    return r;
}
__device__ __forceinline__ void mma_tf32(float c[4], uint2 a01, uint2 a23,
                                         uint2 b01) {
    asm volatile(
        "mma.sync.aligned.m16n8k8.row.col.f32.tf32.tf32.f32 "
        "{%0,%1,%2,%3}, {%4,%5,%6,%7}, {%8,%9}, {%0,%1,%2,%3};"
        : "+f"(c[0]), "+f"(c[1]), "+f"(c[2]), "+f"(c[3])
        : "r"(a01.x), "r"(a01.y), "r"(a23.x), "r"(a23.y),
          "r"(b01.x), "r"(b01.y));
}

// Fragment-major smem tiles.
// A-operand tile (16m x 8k) = 128 words: word = khi*64 + ((lane^swz)<<1) + r
//   lane = (m&7)*4 + (k&3), khi = (k>>2)&1, r = (m>>3)&1
//   -> thread loads a0,a1 as uint2 at +((lane^swz)<<1), a2,a3 at +64.
// B-operand tile (8n x 8k) = 64 words: word = ((lane^swz)<<1) + khi
//   lane = (n&7)*4 + (k&3)  -> thread loads b0,b1 as one uint2.
#define SWZ(x) ((((x) & 3) << 2) | ((((x) >> 2) & 1) << 1))

__device__ __forceinline__ int a_word(int mr, int kk, int swz) {
    const int lane = ((mr & 7) << 2) | (kk & 3);
    return (((kk >> 2) & 1) << 6) + ((lane ^ swz) << 1) + ((mr >> 3) & 1);
}
__device__ __forceinline__ int b_word(int nn, int kk, int swz) {
    const int lane = ((nn & 7) << 2) | (kk & 3);
    return ((lane ^ swz) << 1) + ((kk >> 2) & 1);
}

// ---------------------------------------------------------------------------
// Mask pack: bit j of word w = (mask[w*32+j] != 0)
// ---------------------------------------------------------------------------
__global__ void pack_mask(const int* __restrict__ m, uint32_t* __restrict__ pk) {
    const int i = blockIdx.x * blockDim.x + threadIdx.x;
    const unsigned bal = __ballot_sync(0xffffffffu, m[i] != 0);
    if ((i & 31) == 0) pk[i >> 5] = bal;
}

// ---------------------------------------------------------------------------
// TF32 GEMM: C[M,N] = A[M,K] @ W[K,N] + bias[N]
// 128x128 block, BK=16 double buffered, 8 warps (2x4), warp tile 64x32.
// Fragment-major smem: A tiles (8 mt x 2 kt), B tiles (16 nt x 2 kt).
// ---------------------------------------------------------------------------
#define GBK 16
__global__ __launch_bounds__(256, 2) void tf32_gemm_bias(
    int M, int N, int K,
    const float* __restrict__ A, const float* __restrict__ W,
    const float* __restrict__ bias, float* __restrict__ C)
{
    __shared__ uint32_t Asf[2][2048];   // [mt*2+kt]*128 + a_word
    __shared__ uint32_t Bsf[2][2048];   // [nt*2+kt]*64 + b_word

    const int tid  = threadIdx.x;
    const int lane = tid & 31;
    const int warp = tid >> 5;
    const int wm = warp >> 2;      // m base wm*64
    const int wn = warp & 3;       // n base wn*32
    const int g  = lane >> 2;
    const int tig = lane & 3;

    const int bx = blockIdx.x, by = blockIdx.y;
    A += (size_t)by * 128 * K;
    W += bx * 128;
    C += (size_t)by * 128 * N + bx * 128;

    // Staging assignments
    const int ar = tid >> 1;           // A row 0..127
    const int ah = tid & 1;            // A k-half (ktile)
    const int br = tid >> 4;           // B k-row 0..15
    const int bn8 = tid & 15;          // B ntile

    // Precompute staging smem offsets (swizzled word indices are tid-constant)
    uint32_t* const abase = &Asf[0][((ar >> 4) * 2 + ah) * 128];
    const int amr = ar & 15;
    uint32_t* const bbase = &Bsf[0][(bn8 * 2 + (br >> 3)) * 64];
    const int bkk = br & 7;
    const int bsw = SWZ(bn8);

    float acc[4][4][4];
#pragma unroll
    for (int mi = 0; mi < 4; mi++)
#pragma unroll
        for (int ni = 0; ni < 4; ni++)
#pragma unroll
            for (int j = 0; j < 4; j++) acc[mi][ni][j] = 0.f;

    float4 pa0, pa1, pb0, pb1;

    // ---- prologue: fetch + stage tile 0 ----
    pa0 = *(const float4*)(A + (size_t)ar * K + ah * 8);
    pa1 = *(const float4*)(A + (size_t)ar * K + ah * 8 + 4);
    pb0 = *(const float4*)(W + (size_t)br * N + bn8 * 8);
    pb1 = *(const float4*)(W + (size_t)br * N + bn8 * 8 + 4);
    {
        abase[a_word(amr, 0, 0)] = f2tf(pa0.x);
        abase[a_word(amr, 1, 0)] = f2tf(pa0.y);
        abase[a_word(amr, 2, 0)] = f2tf(pa0.z);
        abase[a_word(amr, 3, 0)] = f2tf(pa0.w);
        abase[a_word(amr, 4, 0)] = f2tf(pa1.x);
        abase[a_word(amr, 5, 0)] = f2tf(pa1.y);
        abase[a_word(amr, 6, 0)] = f2tf(pa1.z);
        abase[a_word(amr, 7, 0)] = f2tf(pa1.w);
        bbase[b_word(0, bkk, bsw)] = f2tf(pb0.x);
        bbase[b_word(1, bkk, bsw)] = f2tf(pb0.y);
        bbase[b_word(2, bkk, bsw)] = f2tf(pb0.z);
        bbase[b_word(3, bkk, bsw)] = f2tf(pb0.w);
        bbase[b_word(4, bkk, bsw)] = f2tf(pb1.x);
        bbase[b_word(5, bkk, bsw)] = f2tf(pb1.y);
        bbase[b_word(6, bkk, bsw)] = f2tf(pb1.z);
        bbase[b_word(7, bkk, bsw)] = f2tf(pb1.w);
    }
    __syncthreads();

    int buf = 0;
    const int nTiles = K / GBK;
    for (int kt = 0; kt < nTiles; kt++) {
        const int kn = (kt + 1) * GBK;
        if (kn < K) {
            pa0 = *(const float4*)(A + (size_t)ar * K + kn + ah * 8);
            pa1 = *(const float4*)(A + (size_t)ar * K + kn + ah * 8 + 4);
            pb0 = *(const float4*)(W + (size_t)(kn + br) * N + bn8 * 8);
            pb1 = *(const float4*)(W + (size_t)(kn + br) * N + bn8 * 8 + 4);
        }

#pragma unroll
        for (int ks = 0; ks < 2; ks++) {
            uint2 a01[4], a23[4];
#pragma unroll
            for (int mi = 0; mi < 4; mi++) {
                const uint32_t* ab =
                    &Asf[buf][((wm * 4 + mi) * 2 + ks) * 128 + (lane << 1)];
                a01[mi] = *(const uint2*)(ab);
                a23[mi] = *(const uint2*)(ab + 64);
            }
#pragma unroll
            for (int ni = 0; ni < 4; ni++) {
                const int nt = wn * 4 + ni;
                const uint2 b01 = *(const uint2*)(
                    &Bsf[buf][(nt * 2 + ks) * 64 + ((lane ^ SWZ(nt)) << 1)]);
#pragma unroll
                for (int mi = 0; mi < 4; mi++)
                    mma_tf32(acc[mi][ni], a01[mi], a23[mi], b01);
            }
        }

        if (kn < K) {
            uint32_t* ab2 = abase + (buf ^ 1) * 2048;
            uint32_t* bb2 = bbase + (buf ^ 1) * 2048;
            ab2[a_word(amr, 0, 0)] = f2tf(pa0.x);
            ab2[a_word(amr, 1, 0)] = f2tf(pa0.y);
            ab2[a_word(amr, 2, 0)] = f2tf(pa0.z);
            ab2[a_word(amr, 3, 0)] = f2tf(pa0.w);
            ab2[a_word(amr, 4, 0)] = f2tf(pa1.x);
            ab2[a_word(amr, 5, 0)] = f2tf(pa1.y);
            ab2[a_word(amr, 6, 0)] = f2tf(pa1.z);
            ab2[a_word(amr, 7, 0)] = f2tf(pa1.w);
            bb2[b_word(0, bkk, bsw)] = f2tf(pb0.x);
            bb2[b_word(1, bkk, bsw)] = f2tf(pb0.y);
            bb2[b_word(2, bkk, bsw)] = f2tf(pb0.z);
            bb2[b_word(3, bkk, bsw)] = f2tf(pb0.w);
            bb2[b_word(4, bkk, bsw)] = f2tf(pb1.x);
            bb2[b_word(5, bkk, bsw)] = f2tf(pb1.y);
            bb2[b_word(6, bkk, bsw)] = f2tf(pb1.z);
            bb2[b_word(7, bkk, bsw)] = f2tf(pb1.w);
            buf ^= 1;
            __syncthreads();
        }
    }

    // Epilogue: c0 (g, 2t), c1 (g, 2t+1), c2 (g+8, 2t), c3 (g+8, 2t+1)
#pragma unroll
    for (int mi = 0; mi < 4; mi++) {
#pragma unroll
        for (int ni = 0; ni < 4; ni++) {
            const int row = wm * 64 + mi * 16 + g;
            const int col = wn * 32 + ni * 8 + 2 * tig;
            const float bz0 = bias[bx * 128 + col];
            const float bz1 = bias[bx * 128 + col + 1];
            float2 o0 = make_float2(acc[mi][ni][0] + bz0, acc[mi][ni][1] + bz1);
            float2 o1 = make_float2(acc[mi][ni][2] + bz0, acc[mi][ni][3] + bz1);
            *(float2*)(&C[(size_t)row * N + col]) = o0;
            *(float2*)(&C[(size_t)(row + 8) * N + col]) = o1;
        }
    }
}

// ---------------------------------------------------------------------------
// Flash attention, TF32 mma, fragment-major smem, no-max softmax.
// Reference algebra: attn = exp(s)/(sum_unmasked exp(s) + n_masked * 1.0).
// Block: 128 q-rows for one (b,h); 8 warps, warp owns 16 q-rows (1 qtile).
// K-tile: 64 keys.
// ---------------------------------------------------------------------------
#define ATTN_SMEM_WORDS (8192 + 4096 + 4096 + 8192)   // Q,K,V,P = 96 KB

__global__ __launch_bounds__(256, 2) void attn_mma(
    const float* __restrict__ qkv, const uint32_t* __restrict__ mpk,
    float* __restrict__ ctx)
{
    extern __shared__ uint32_t dsm[];
    uint32_t* Qsf = dsm;             // [qt8][dt8] A-tiles (128 w each)
    uint32_t* Ksf = Qsf + 8192;      // [nt8][dt8] B-tiles (64 w each)
    uint32_t* Vsf = Ksf + 4096;      // [ntd8][kt8] B-tiles
    uint32_t* Psf = Vsf + 4096;      // [qt8][kt8] A-tiles

    const int tid  = threadIdx.x;
    const int lane = tid & 31;
    const int warp = tid >> 5;
    const int g  = lane >> 2;
    const int tig = lane & 3;

    const int bh = blockIdx.y;
    const int bb = bh >> 4, h = bh & 15;
    const int q0 = blockIdx.x * 128;

    const float* Qg = qkv + (size_t)bb * Ln * 3 * Dn + h * 64;
    const float* Kg = Qg + Dn;
    const float* Vg = Qg + 2 * Dn;

    // Stage Q (128 q x 64 d) into fragment-major A-tiles
    for (int it = 0; it < 8; it++) {
        const int idx = tid + it * 256;      // 2048 float4
        const int q = idx >> 4, d4 = (idx & 15) * 4;
        const float4 v = *(const float4*)(Qg + (size_t)(q0 + q) * 3072 + d4);
        uint32_t* base = Qsf + ((q >> 4) * 8 + (d4 >> 3)) * 128;
        const int mr = q & 15, dlo = d4 & 7, sw = SWZ(d4 >> 3);
        base[a_word(mr, dlo + 0, sw)] = f2tf(v.x);
        base[a_word(mr, dlo + 1, sw)] = f2tf(v.y);
        base[a_word(mr, dlo + 2, sw)] = f2tf(v.z);
        base[a_word(mr, dlo + 3, sw)] = f2tf(v.w);
    }

    float o[8][4];
    float l_i[2] = {0.f, 0.f};
#pragma unroll
    for (int ni = 0; ni < 8; ni++)
#pragma unroll
        for (int j = 0; j < 4; j++) o[ni][j] = 0.f;

    for (int ktl = 0; ktl < Ln / 64; ktl++) {
        const int kb = ktl * 64;
        __syncthreads();   // prev compute done (iter0: Q staged) before restage

        // Stage K (B-op: n=kcol, k=d) and V (B-op: n=d, k=kcol)
        for (int it = 0; it < 4; it++) {
            const int idx = tid + it * 256;  // 1024 float4 each
            const int kk = idx >> 4, d4 = (idx & 15) * 4;
            const int dlo = d4 & 7;
            const int dt = d4 >> 3;
            const int sw = SWZ(dt);
            const float4 kv = *(const float4*)(Kg + (size_t)(kb + kk) * 3072 + d4);
            uint32_t* kbase = Ksf + ((kk >> 3) * 8 + dt) * 64;
            kbase[b_word(kk & 7, dlo + 0, sw)] = f2tf(kv.x);
            kbase[b_word(kk & 7, dlo + 1, sw)] = f2tf(kv.y);
            kbase[b_word(kk & 7, dlo + 2, sw)] = f2tf(kv.z);
            kbase[b_word(kk & 7, dlo + 3, sw)] = f2tf(kv.w);
            const float4 vv = *(const float4*)(Vg + (size_t)(kb + kk) * 3072 + d4);
            uint32_t* vbase = Vsf + (dt * 8 + (kk >> 3)) * 64;
            vbase[b_word(dlo + 0, kk & 7, sw)] = f2tf(vv.x);
            vbase[b_word(dlo + 1, kk & 7, sw)] = f2tf(vv.y);
            vbase[b_word(dlo + 2, kk & 7, sw)] = f2tf(vv.z);
            vbase[b_word(dlo + 3, kk & 7, sw)] = f2tf(vv.w);
        }
        __syncthreads();

        // S = Q @ K^T : warp computes 16q x 64k
        float s[8][4];
#pragma unroll
        for (int ni = 0; ni < 8; ni++)
#pragma unroll
            for (int j = 0; j < 4; j++) s[ni][j] = 0.f;

#pragma unroll
        for (int dt = 0; dt < 8; dt++) {
            const uint32_t* qb = Qsf + (warp * 8 + dt) * 128;
            const int lq = (lane ^ SWZ(dt)) << 1;
            const uint2 a01 = *(const uint2*)(qb + lq);
            const uint2 a23 = *(const uint2*)(qb + 64 + lq);
#pragma unroll
            for (int ni = 0; ni < 8; ni++) {
                const uint2 b01 = *(const uint2*)(
                    Ksf + (ni * 8 + dt) * 64 + ((lane ^ SWZ(dt)) << 1));
                mma_tf32(s[ni], a01, a23, b01);
            }
        }

        // Mask (packed bits) + exp; no max subtraction needed.
        // masked: contributes 1.0 to denominator, 0 to P.
#pragma unroll
        for (int ri = 0; ri < 2; ri++) {
            const int qrow = q0 + warp * 16 + g + ri * 8;
            const uint2 mw = *(const uint2*)(
                mpk + (((size_t)(bb * Ln + qrow)) << 6) + (kb >> 5));
#pragma unroll
            for (int ni = 0; ni < 8; ni++) {
                const uint32_t w = (ni < 4) ? mw.x : mw.y;
                const int sh = ((ni & 3) << 3) + 2 * tig;
                const bool m0 = (w >> sh) & 1;
                const bool m1 = (w >> (sh + 1)) & 1;
                // exp(s/8) = 2^(s * 0.125*log2(e))
                const float e0 = ex2(s[ni][ri * 2 + 0] * 0.180336880f);
                const float e1 = ex2(s[ni][ri * 2 + 1] * 0.180336880f);
                l_i[ri] += (m0 ? e0 : 1.0f) + (m1 ? e1 : 1.0f);
                s[ni][ri * 2 + 0] = m0 ? e0 : 0.0f;
                s[ni][ri * 2 + 1] = m1 ? e1 : 0.0f;
            }
        }

        // Store P (A-op for PV) into this warp's own tiles -> __syncwarp only
#pragma unroll
        for (int ni = 0; ni < 8; ni++) {
            uint32_t* pb = Psf + (warp * 8 + ni) * 128;
            const int khi = (tig >> 1) & 1;
            const int sw = SWZ(ni);
            const int la0 = (g << 2) | ((2 * tig) & 3);
            const int la1 = (g << 2) | ((2 * tig + 1) & 3);
            uint2 u0, u1;
            u0.x = f2tf(s[ni][0]); u0.y = f2tf(s[ni][2]);
            u1.x = f2tf(s[ni][1]); u1.y = f2tf(s[ni][3]);
            *(uint2*)(pb + khi * 64 + ((la0 ^ sw) << 1)) = u0;
            *(uint2*)(pb + khi * 64 + ((la1 ^ sw) << 1)) = u1;
        }
        __syncwarp();

        // O += P @ V : warp computes 16q x 64d over 64 kcols
#pragma unroll
        for (int kt8 = 0; kt8 < 8; kt8++) {
            const uint32_t* pb = Psf + (warp * 8 + kt8) * 128;
            const int lp = (lane ^ SWZ(kt8)) << 1;
            const uint2 a01 = *(const uint2*)(pb + lp);
            const uint2 a23 = *(const uint2*)(pb + 64 + lp);
#pragma unroll
            for (int ni = 0; ni < 8; ni++) {
                const uint2 b01 = *(const uint2*)(
                    Vsf + (ni * 8 + kt8) * 64 + ((lane ^ SWZ(ni)) << 1));
                mma_tf32(o[ni], a01, a23, b01);
            }
        }
    }

    // Reduce l over the 4 tig lanes of each row group
#pragma unroll
    for (int ri = 0; ri < 2; ri++) {
        l_i[ri] += __shfl_xor_sync(0xffffffffu, l_i[ri], 1);
        l_i[ri] += __shfl_xor_sync(0xffffffffu, l_i[ri], 2);
    }
    const float inv0 = 1.0f / l_i[0];
    const float inv1 = 1.0f / l_i[1];
    const int row0 = q0 + warp * 16 + g;
#pragma unroll
    for (int ni = 0; ni < 8; ni++) {
        const int col = h * 64 + ni * 8 + 2 * tig;
        float2 o0 = make_float2(o[ni][0] * inv0, o[ni][1] * inv0);
        float2 o1 = make_float2(o[ni][2] * inv1, o[ni][3] * inv1);
        *(float2*)(ctx + (size_t)(bb * Ln + row0) * Dn + col) = o0;
        *(float2*)(ctx + (size_t)(bb * Ln + row0 + 8) * Dn + col) = o1;
    }
}

// ---------------------------------------------------------------------------
extern "C" void kernel_launch(void* const* d_in, const int* in_sizes, int n_in,
                              void* d_out, int out_size)
{
    const float* x   = (const float*)d_in[0];  // (B, L, D) fp32
    const int*   msk = (const int*)d_in[1];    // (B, L, L) int32
    const float* W1  = (const float*)d_in[2];  // (D, 3D)
    const float* b1  = (const float*)d_in[3];  // (3D,)
    const float* W2  = (const float*)d_in[4];  // (D, D)
    const float* b2  = (const float*)d_in[5];  // (D,)
    float* out = (float*)d_out;                // (B, L, D)

    float *qkv = nullptr, *ctx = nullptr;
    uint32_t* mpk = nullptr;
    cudaGetSymbolAddress((void**)&qkv, g_qkv);
    cudaGetSymbolAddress((void**)&ctx, g_ctx);
    cudaGetSymbolAddress((void**)&mpk, g_mpack);

    const int M = Bn * Ln;  // 8192
    const int attnSmem = ATTN_SMEM_WORDS * 4;  // 98304 bytes
    cudaFuncSetAttribute(attn_mma, cudaFuncAttributeMaxDynamicSharedMemorySize,
                         attnSmem);

    // 0) Pack mask into bits
    pack_mask<<<(Bn * Ln * Ln) / 256, 256>>>(msk, mpk);

    // 1) QKV projection: (8192,1024) @ (1024,3072) + b1
    tf32_gemm_bias<<<dim3(3 * Dn / 128, M / 128), 256>>>(M, 3 * Dn, Dn, x, W1, b1, qkv);

    // 2) Masked attention per (b,h), 128 q-rows per block
    attn_mma<<<dim3(Ln / 128, Bn * Hn), 256, attnSmem>>>(qkv, mpk, ctx);

    // 3) Output projection: (8192,1024) @ (1024,1024) + b2
    tf32_gemm_bias<<<dim3(Dn / 128, M / 128), 256>>>(M, Dn, Dn, ctx, W2, b2, out);
}

// round 10
// speedup vs baseline: 6.2290x; 2.1600x over previous
#include <cuda_runtime.h>
#include <cuda_fp16.h>
#include <cstdint>

// Problem shape (fixed by the reference)
#define Bn 4
#define Ln 2048
#define Dn 1024
#define Hn 16

// Scratch (allocation-free rule: __device__ globals)
__device__ __half   g_x16[(size_t)Bn * Ln * Dn];        // 16.8 MB  x -> fp16
__device__ __half   g_w1t[(size_t)3 * Dn * Dn];         //  6.3 MB  W1^T fp16
__device__ __half   g_w2t[(size_t)Dn * Dn];             //  2.1 MB  W2^T fp16
__device__ __half   g_qkv[(size_t)Bn * Ln * 3 * Dn];    // 50.3 MB  qkv fp16
__device__ __half   g_ctx[(size_t)Bn * Ln * Dn];        // 16.8 MB  ctx fp16
__device__ uint32_t g_mpack[(size_t)Bn * Ln * Ln / 32]; //  2.1 MB  packed mask

// ---------------------------------------------------------------------------
// Helpers (baseline-PTX only: sm_80-era features, safe for .target sm_100)
// ---------------------------------------------------------------------------
__device__ __forceinline__ uint32_t packh2(float lo, float hi) {
    uint32_t r;  // cvt.rn.f16x2.f32 d, a, b : d.hi=a, d.lo=b
    asm("cvt.rn.f16x2.f32 %0, %1, %2;" : "=r"(r) : "f"(hi), "f"(lo));
    return r;
}
__device__ __forceinline__ float ex2(float x) {
    float r;
    asm("ex2.approx.ftz.f32 %0, %1;" : "=f"(r) : "f"(x));
    return r;
}
__device__ __forceinline__ uint32_t s2u(const void* p) {
    uint32_t a;
    asm("{ .reg .u64 t; cvta.to.shared.u64 t, %1; cvt.u32.u64 %0, t; }"
        : "=r"(a) : "l"(p));
    return a;
}
__device__ __forceinline__ void mma_f16(float c[4], uint32_t a0, uint32_t a1,
                                        uint32_t a2, uint32_t a3,
                                        uint32_t b0, uint32_t b1) {
    asm volatile(
        "mma.sync.aligned.m16n8k16.row.col.f32.f16.f16.f32 "
        "{%0,%1,%2,%3}, {%4,%5,%6,%7}, {%8,%9}, {%0,%1,%2,%3};"
        : "+f"(c[0]), "+f"(c[1]), "+f"(c[2]), "+f"(c[3])
        : "r"(a0), "r"(a1), "r"(a2), "r"(a3), "r"(b0), "r"(b1));
}
#define LDSM_X4(r, addr)                                                     \
    asm volatile("ldmatrix.sync.aligned.m8n8.x4.shared.b16 {%0,%1,%2,%3}, [%4];" \
        : "=r"((r)[0]), "=r"((r)[1]), "=r"((r)[2]), "=r"((r)[3]) : "r"(addr))
#define LDSM_X4T(r, addr)                                                    \
    asm volatile("ldmatrix.sync.aligned.m8n8.x4.trans.shared.b16 {%0,%1,%2,%3}, [%4];" \
        : "=r"((r)[0]), "=r"((r)[1]), "=r"((r)[2]), "=r"((r)[3]) : "r"(addr))
__device__ __forceinline__ void cpa16(uint32_t s, const void* g) {
    uint64_t ga;
    asm("cvta.to.global.u64 %0, %1;" : "=l"(ga) : "l"(g));
    asm volatile("cp.async.cg.shared.global [%0], [%1], 16;" :: "r"(s), "l"(ga));
}
#define CP_COMMIT asm volatile("cp.async.commit_group;" ::: "memory")
#define CP_WAIT0  asm volatile("cp.async.wait_group 0;" ::: "memory")
#define CP_WAIT1  asm volatile("cp.async.wait_group 1;" ::: "memory")
#define CP_WAIT2  asm volatile("cp.async.wait_group 2;" ::: "memory")

// ---------------------------------------------------------------------------
// Prep kernels
// ---------------------------------------------------------------------------
__global__ void pack_mask(const int* __restrict__ m, uint32_t* __restrict__ pk) {
    const int i = blockIdx.x * blockDim.x + threadIdx.x;
    const unsigned bal = __ballot_sync(0xffffffffu, m[i] != 0);
    if ((i & 31) == 0) pk[i >> 5] = bal;
}
__global__ void cvt_half(const float* __restrict__ in, __half* __restrict__ out) {
    const int i = (blockIdx.x * blockDim.x + threadIdx.x) * 4;
    const float4 v = *(const float4*)(in + i);
    uint2 o;
    o.x = packh2(v.x, v.y);
    o.y = packh2(v.z, v.w);
    *(uint2*)(out + i) = o;
}
// W[K][N] f32 -> Wt[N][K] fp16 (32x32 smem transpose, 256 threads)
__global__ void cvt_wT(const float* __restrict__ W, __half* __restrict__ Wt,
                       int K, int N) {
    __shared__ float ts[32][33];
    const int n0 = blockIdx.x * 32, k0 = blockIdx.y * 32;
    const int tx = threadIdx.x & 31, ty = threadIdx.x >> 5;
#pragma unroll
    for (int i = 0; i < 4; i++)
        ts[ty + i * 8][tx] = W[(size_t)(k0 + ty + i * 8) * N + n0 + tx];
    __syncthreads();
#pragma unroll
    for (int i = 0; i < 4; i++)
        Wt[(size_t)(n0 + ty + i * 8) * K + k0 + tx] =
            __float2half_rn(ts[tx][ty + i * 8]);
}

// ---------------------------------------------------------------------------
// FP16 GEMM: C[M,N] = A[M,K](fp16) @ Bt[N,K](fp16)^T + bias; C fp16 or f32.
// 128x128 CTA tile, BK=32, 3-stage cp.async pipeline, 8 warps (2x4),
// warp tile 64x32, ldmatrix fragments. Smem rows padded to 80B (bank-clean).
// ---------------------------------------------------------------------------
#define GST 20480   // stage = A 128x40h (10240B) + B 128x40h
__global__ __launch_bounds__(256, 2) void gemm16(
    int M, int N, int K,
    const __half* __restrict__ A, const __half* __restrict__ Bt,
    const float* __restrict__ bias, __half* __restrict__ Ch,
    float* __restrict__ Cf)
{
    extern __shared__ char sm[];
    const uint32_t sb = s2u(sm);
    const int tid = threadIdx.x, lane = tid & 31, warp = tid >> 5;
    const int wm = warp >> 2, wn = warp & 3, g = lane >> 2, tig = lane & 3;
    const int bx = blockIdx.x, by = blockIdx.y;
    const __half* Ag = A + (size_t)by * 128 * K;
    const __half* Bg = Bt + (size_t)bx * 128 * K;

    const int srow = tid >> 1;            // staging row 0..127
    const int skc = (tid & 1) * 2;        // chunk pair base 0/2

    float acc[4][4][4];
#pragma unroll
    for (int mi = 0; mi < 4; mi++)
#pragma unroll
        for (int ni = 0; ni < 4; ni++)
#pragma unroll
            for (int j = 0; j < 4; j++) acc[mi][ni][j] = 0.f;

    const int nT = K / 32;
    // prologue: stages 0,1
#pragma unroll
    for (int t = 0; t < 2; t++) {
        const int k0 = t * 32;
        const uint32_t st = sb + t * GST;
        const __half* ag = Ag + (size_t)srow * K + k0 + skc * 8;
        cpa16(st + srow * 80 + skc * 16, ag);
        cpa16(st + srow * 80 + (skc + 1) * 16, ag + 8);
        const __half* bg = Bg + (size_t)srow * K + k0 + skc * 8;
        cpa16(st + 10240 + srow * 80 + skc * 16, bg);
        cpa16(st + 10240 + srow * 80 + (skc + 1) * 16, bg + 8);
        CP_COMMIT;
    }

    for (int t = 0; t < nT; t++) {
        __syncthreads();
        if (t + 2 < nT) {
            const int k0 = (t + 2) * 32;
            const uint32_t st = sb + ((t + 2) % 3) * GST;
            const __half* ag = Ag + (size_t)srow * K + k0 + skc * 8;
            cpa16(st + srow * 80 + skc * 16, ag);
            cpa16(st + srow * 80 + (skc + 1) * 16, ag + 8);
            const __half* bg = Bg + (size_t)srow * K + k0 + skc * 8;
            cpa16(st + 10240 + srow * 80 + skc * 16, bg);
            cpa16(st + 10240 + srow * 80 + (skc + 1) * 16, bg + 8);
            CP_COMMIT;
            CP_WAIT2;
        } else if (t + 1 < nT) {
            CP_WAIT1;
        } else {
            CP_WAIT0;
        }
        __syncthreads();

        const uint32_t st = sb + (t % 3) * GST;
        uint32_t bt[4][4];
#pragma unroll
        for (int ni = 0; ni < 4; ni++)
            LDSM_X4(bt[ni], st + 10240 + (wn * 32 + ni * 8 + (lane & 7)) * 80
                            + (lane >> 3) * 16);
#pragma unroll
        for (int ks = 0; ks < 2; ks++) {
            uint32_t a4[4][4];
#pragma unroll
            for (int mi = 0; mi < 4; mi++)
                LDSM_X4(a4[mi], st + (wm * 64 + mi * 16 + (lane & 15)) * 80
                                + ks * 32 + (lane >> 4) * 16);
#pragma unroll
            for (int mi = 0; mi < 4; mi++)
#pragma unroll
                for (int ni = 0; ni < 4; ni++)
                    mma_f16(acc[mi][ni], a4[mi][0], a4[mi][1], a4[mi][2],
                            a4[mi][3], bt[ni][2 * ks], bt[ni][2 * ks + 1]);
        }
    }

    // epilogue: c0 (g, 2t), c1 (g, 2t+1), c2 (g+8, 2t), c3 (g+8, 2t+1)
#pragma unroll
    for (int mi = 0; mi < 4; mi++) {
#pragma unroll
        for (int ni = 0; ni < 4; ni++) {
            const int row = by * 128 + wm * 64 + mi * 16 + g;
            const int col = bx * 128 + wn * 32 + ni * 8 + 2 * tig;
            const float bz0 = bias[col], bz1 = bias[col + 1];
            const float f0 = acc[mi][ni][0] + bz0, f1 = acc[mi][ni][1] + bz1;
            const float f2 = acc[mi][ni][2] + bz0, f3 = acc[mi][ni][3] + bz1;
            if (Cf) {
                *(float2*)(&Cf[(size_t)row * N + col]) = make_float2(f0, f1);
                *(float2*)(&Cf[(size_t)(row + 8) * N + col]) = make_float2(f2, f3);
            } else {
                *(uint32_t*)(&Ch[(size_t)row * N + col]) = packh2(f0, f1);
                *(uint32_t*)(&Ch[(size_t)(row + 8) * N + col]) = packh2(f2, f3);
            }
        }
    }
}

// ---------------------------------------------------------------------------
// FP16 flash attention, no-max softmax (reference algebra:
//   attn = exp(s)/(sum_unmasked exp(s) + n_masked)), packed-bit mask.
// Block: 128 q (8 warps x 16q) for one (b,h). K-tile 64, double-buffered
// cp.async. P stays in registers (C-frag -> A-frag fp16 conversion).
// Smem: Q 128x72h(144B rows)=18432, K/V[2] 64x72h=9216 each -> 55296 B.
// ---------------------------------------------------------------------------
#define AT_SMEM 55296
#define QOFF 0
#define KOFF(b) (18432 + (b) * 18432)
#define VOFF(b) (KOFF(b) + 9216)

__global__ __launch_bounds__(256, 2) void attn16(
    const __half* __restrict__ qkv, const uint32_t* __restrict__ mpk,
    __half* __restrict__ ctx)
{
    extern __shared__ char sm[];
    const uint32_t sb = s2u(sm);
    const int tid = threadIdx.x, lane = tid & 31, warp = tid >> 5;
    const int g = lane >> 2, tig = lane & 3;
    const int bh = blockIdx.y;
    const int bb = bh >> 4, h = bh & 15;
    const int q0 = blockIdx.x * 128;
    const size_t base = (size_t)bb * Ln * 3 * Dn + h * 64;

    // prologue: Q tile + KV tile 0 as one commit group
#pragma unroll
    for (int i = 0; i < 4; i++) {
        const int c = tid + i * 256;           // 1024 chunks
        const int row = c >> 3, dc = c & 7;
        cpa16(sb + QOFF + row * 144 + dc * 16,
              qkv + base + (size_t)(q0 + row) * 3072 + dc * 8);
    }
#pragma unroll
    for (int i = 0; i < 2; i++) {
        const int c = tid + i * 256;           // 512 chunks each
        const int row = c >> 3, dc = c & 7;
        cpa16(sb + KOFF(0) + row * 144 + dc * 16,
              qkv + base + (size_t)row * 3072 + Dn + dc * 8);
        cpa16(sb + VOFF(0) + row * 144 + dc * 16,
              qkv + base + (size_t)row * 3072 + 2 * Dn + dc * 8);
    }
    CP_COMMIT;

    float o[8][4];
    float l_i[2] = {0.f, 0.f};
#pragma unroll
    for (int nd = 0; nd < 8; nd++)
#pragma unroll
        for (int j = 0; j < 4; j++) o[nd][j] = 0.f;

    const int nT = Ln / 64;
    for (int t = 0; t < nT; t++) {
        __syncthreads();
        if (t + 1 < nT) {
            const int kb = (t + 1) * 64;
            const int buf = (t + 1) & 1;
#pragma unroll
            for (int i = 0; i < 2; i++) {
                const int c = tid + i * 256;
                const int row = c >> 3, dc = c & 7;
                cpa16(sb + KOFF(buf) + row * 144 + dc * 16,
                      qkv + base + (size_t)(kb + row) * 3072 + Dn + dc * 8);
                cpa16(sb + VOFF(buf) + row * 144 + dc * 16,
                      qkv + base + (size_t)(kb + row) * 3072 + 2 * Dn + dc * 8);
            }
            CP_COMMIT;
            CP_WAIT1;
        } else {
            CP_WAIT0;
        }
        __syncthreads();

        const int buf = t & 1;
        // S = Q @ K^T (16q x 64k per warp), fp32 acc
        float s[8][4];
#pragma unroll
        for (int ni = 0; ni < 8; ni++)
#pragma unroll
            for (int j = 0; j < 4; j++) s[ni][j] = 0.f;

#pragma unroll
        for (int kp = 0; kp < 2; kp++) {       // d halves 0-31 / 32-63
            uint32_t qf0[4], qf1[4];
            LDSM_X4(qf0, sb + QOFF + (warp * 16 + (lane & 15)) * 144
                         + (2 * kp) * 32 + (lane >> 4) * 16);
            LDSM_X4(qf1, sb + QOFF + (warp * 16 + (lane & 15)) * 144
                         + (2 * kp + 1) * 32 + (lane >> 4) * 16);
            uint32_t kbf[8][4];
#pragma unroll
            for (int ni = 0; ni < 8; ni++)
                LDSM_X4(kbf[ni], sb + KOFF(buf) + (ni * 8 + (lane & 7)) * 144
                                 + kp * 64 + (lane >> 3) * 16);
#pragma unroll
            for (int ni = 0; ni < 8; ni++) {
                mma_f16(s[ni], qf0[0], qf0[1], qf0[2], qf0[3],
                        kbf[ni][0], kbf[ni][1]);
                mma_f16(s[ni], qf1[0], qf1[1], qf1[2], qf1[3],
                        kbf[ni][2], kbf[ni][3]);
            }
        }

        // mask + exp (no max subtraction); masked -> denom += 1, P = 0
        const int kb = t * 64;
        uint32_t ap[8][2];
#pragma unroll
        for (int ri = 0; ri < 2; ri++) {
            const int qrow = q0 + warp * 16 + g + ri * 8;
            const uint2 mw = *(const uint2*)(
                mpk + (((size_t)(bb * Ln + qrow)) << 6) + (kb >> 5));
#pragma unroll
            for (int ni = 0; ni < 8; ni++) {
                const uint32_t w = (ni < 4) ? mw.x : mw.y;
                const int sh = ((ni & 3) << 3) + 2 * tig;
                const bool m0 = (w >> sh) & 1;
                const bool m1 = (w >> (sh + 1)) & 1;
                const float e0 = ex2(s[ni][ri * 2 + 0] * 0.180336880f);
                const float e1 = ex2(s[ni][ri * 2 + 1] * 0.180336880f);
                l_i[ri] += (m0 ? e0 : 1.0f) + (m1 ? e1 : 1.0f);
                s[ni][ri * 2 + 0] = m0 ? e0 : 0.0f;
                s[ni][ri * 2 + 1] = m1 ? e1 : 0.0f;
            }
        }
#pragma unroll
        for (int ni = 0; ni < 8; ni++) {
            ap[ni][0] = packh2(s[ni][0], s[ni][1]);   // rows g
            ap[ni][1] = packh2(s[ni][2], s[ni][3]);   // rows g+8
        }

        // O += P @ V (A-frags from registers; V via ldmatrix.trans)
#pragma unroll
        for (int jp = 0; jp < 2; jp++) {       // kcol halves 0-31 / 32-63
            uint32_t vbf[8][4];
#pragma unroll
            for (int nd = 0; nd < 8; nd++)
                LDSM_X4T(vbf[nd], sb + VOFF(buf) + (jp * 32 + lane) * 144
                                  + nd * 16);
#pragma unroll
            for (int j2 = 0; j2 < 2; j2++) {
                const int j = 2 * jp + j2;     // k16 step over kcols
#pragma unroll
                for (int nd = 0; nd < 8; nd++)
                    mma_f16(o[nd], ap[2 * j][0], ap[2 * j][1],
                            ap[2 * j + 1][0], ap[2 * j + 1][1],
                            vbf[nd][2 * j2], vbf[nd][2 * j2 + 1]);
            }
        }
    }

    // reduce denominator over tig lanes; normalize; store ctx fp16
#pragma unroll
    for (int ri = 0; ri < 2; ri++) {
        l_i[ri] += __shfl_xor_sync(0xffffffffu, l_i[ri], 1);
        l_i[ri] += __shfl_xor_sync(0xffffffffu, l_i[ri], 2);
    }
    const float inv0 = 1.0f / l_i[0];
    const float inv1 = 1.0f / l_i[1];
    const int row0 = q0 + warp * 16 + g;
#pragma unroll
    for (int nd = 0; nd < 8; nd++) {
        const int col = h * 64 + nd * 8 + 2 * tig;
        *(uint32_t*)(&ctx[(size_t)(bb * Ln + row0) * Dn + col]) =
            packh2(o[nd][0] * inv0, o[nd][1] * inv0);
        *(uint32_t*)(&ctx[(size_t)(bb * Ln + row0 + 8) * Dn + col]) =
            packh2(o[nd][2] * inv1, o[nd][3] * inv1);
    }
}

// ---------------------------------------------------------------------------
extern "C" void kernel_launch(void* const* d_in, const int* in_sizes, int n_in,
                              void* d_out, int out_size)
{
    const float* x   = (const float*)d_in[0];  // (B, L, D) fp32
    const int*   msk = (const int*)d_in[1];    // (B, L, L) int32
    const float* W1  = (const float*)d_in[2];  // (D, 3D)
    const float* b1  = (const float*)d_in[3];  // (3D,)
    const float* W2  = (const float*)d_in[4];  // (D, D)
    const float* b2  = (const float*)d_in[5];  // (D,)
    float* out = (float*)d_out;                // (B, L, D)

    __half *x16, *w1t, *w2t, *qkv, *ctx;
    uint32_t* mpk;
    cudaGetSymbolAddress((void**)&x16, g_x16);
    cudaGetSymbolAddress((void**)&w1t, g_w1t);
    cudaGetSymbolAddress((void**)&w2t, g_w2t);
    cudaGetSymbolAddress((void**)&qkv, g_qkv);
    cudaGetSymbolAddress((void**)&ctx, g_ctx);
    cudaGetSymbolAddress((void**)&mpk, g_mpack);

    const int M = Bn * Ln;  // 8192
    cudaFuncSetAttribute(gemm16, cudaFuncAttributeMaxDynamicSharedMemorySize,
                         3 * GST);
    cudaFuncSetAttribute(attn16, cudaFuncAttributeMaxDynamicSharedMemorySize,
                         AT_SMEM);

    // 0) prep: mask pack, x->fp16, W1^T/W2^T fp16
    pack_mask<<<(Bn * Ln * Ln) / 256, 256>>>(msk, mpk);
    cvt_half<<<(Bn * Ln * Dn) / 1024, 256>>>(x, x16);
    cvt_wT<<<dim3(3 * Dn / 32, Dn / 32), 256>>>(W1, w1t, Dn, 3 * Dn);
    cvt_wT<<<dim3(Dn / 32, Dn / 32), 256>>>(W2, w2t, Dn, Dn);

    // 1) QKV projection -> fp16 qkv
    gemm16<<<dim3(3 * Dn / 128, M / 128), 256, 3 * GST>>>(
        M, 3 * Dn, Dn, x16, w1t, b1, qkv, nullptr);

    // 2) masked attention -> fp16 ctx
    attn16<<<dim3(Ln / 128, Bn * Hn), 256, AT_SMEM>>>(qkv, mpk, ctx);

    // 3) output projection -> f32 out
    gemm16<<<dim3(Dn / 128, M / 128), 256, 3 * GST>>>(
        M, Dn, Dn, ctx, w2t, b2, nullptr, out);
}